// round 14
// baseline (speedup 1.0000x reference)
#include <cuda_runtime.h>
#include <cuda_bf16.h>

#define BSZ   512
#define TT    200
#define HID   128
#define GG    512
#define EMBD  100
#define VOC   30000
#define NCLS  9

// g_proj layout: per dir, u64[VOC][256]; slot j of row v = {col j, col j+256}
__device__ float g_proj[2][VOC * GG];
__device__ float g_h[2][BSZ * TT * HID];
// U transposed k-paired: [dir][col][k2], entry = {U[2k2][col], U[2k2+1][col]}
__device__ unsigned long long g_Ut[2][GG * 64];
// BN-folded dense: g_Wp[c][d] (c<9, d<256), g_bp[c]
__device__ float g_Wp[NCLS * 256];
__device__ float g_bp[16];

typedef unsigned long long u64;

__device__ __forceinline__ u64 pk2(float lo, float hi) {
    u64 r; asm("mov.b64 %0, {%1,%2};" : "=l"(r) : "f"(lo), "f"(hi)); return r;
}
__device__ __forceinline__ void upk2(u64 v, float& lo, float& hi) {
    asm("mov.b64 {%0,%1}, %2;" : "=f"(lo), "=f"(hi) : "l"(v));
}
__device__ __forceinline__ u64 fma2(u64 a, u64 b, u64 c) {
    u64 d; asm("fma.rn.f32x2 %0, %1, %2, %3;" : "=l"(d) : "l"(a), "l"(b), "l"(c)); return d;
}
__device__ __forceinline__ float hadd2(u64 v) {
    float lo, hi; upk2(v, lo, hi); return lo + hi;
}
__device__ __forceinline__ float sigf(float x) {
    return __fdividef(1.0f, 1.0f + __expf(-x));
}

// ---------------------------------------------------------------------------
// U transpose: g_Ut[dir][col*64+k2] = {U[2k2][col], U[2k2+1][col]}
// ---------------------------------------------------------------------------
__global__ void utrans_kernel(const float* __restrict__ Uf, const float* __restrict__ Ub)
{
    const int k2  = blockIdx.x & 63;
    const int dir = blockIdx.x >> 6;
    const float* U = dir ? Ub : Uf;
    const int col = threadIdx.x;
    g_Ut[dir][col * 64 + k2] = pk2(U[2 * k2 * GG + col], U[(2 * k2 + 1) * GG + col]);
}

// ---------------------------------------------------------------------------
// Head prep: fold BN into dense.
// ---------------------------------------------------------------------------
__global__ void headprep_kernel(const float* __restrict__ gamma, const float* __restrict__ beta,
                                const float* __restrict__ mean,  const float* __restrict__ var,
                                const float* __restrict__ Wd,    const float* __restrict__ bd)
{
    __shared__ float sc[256], sh[256];
    const int tid = threadIdx.x;
    float rs = rsqrtf(var[tid] + 1e-3f);
    float s  = rs * gamma[tid];
    sc[tid] = s;
    sh[tid] = beta[tid] - mean[tid] * s;
    __syncthreads();
    for (int idx = tid; idx < NCLS * 256; idx += 256) {
        int c = idx >> 8, d = idx & 255;
        g_Wp[idx] = sc[d] * Wd[d * NCLS + c];
    }
    if (tid < NCLS) {
        float acc = bd[tid];
        for (int d = 0; d < 256; d++) acc += sh[d] * Wd[d * NCLS + tid];
        g_bp[tid] = acc;
    }
}

// ---------------------------------------------------------------------------
// proj v5: 4 rows per warp — LDS:fma ratio cut 2.5x vs v4.
// CTA tile: 32 vocab rows x 32 slots. block 256 = 8 warps; lane = slot,
// warp = 4 rows (r0 = w*4). All 50 k2 in smem up front, one sync.
// Per warp-k2: 2 broadcast LDS.128 (E) + 2 per-lane LDS.64 (W) + 16 fma2.
// smem: W2[50*64] u64 (25600) + e2[50*34] u64 (13600) = 39200 -> 3 CTAs/SM.
// grid = 938 rowtiles x 8 slottiles x 2 dirs = 15008.
// ---------------------------------------------------------------------------
#define EP2 34
__global__ __launch_bounds__(256, 3)
void proj_kernel(const float* __restrict__ emb,
                 const float* __restrict__ Wf, const float* __restrict__ bf,
                 const float* __restrict__ Wb, const float* __restrict__ bb)
{
    __shared__ u64 W2[50 * 64];     // [k2][c6]: c6<32 -> col, c6>=32 -> col+256
    __shared__ u64 e2[50 * EP2];    // [k2][row pairs of k]

    const int tid  = threadIdx.x;
    const int lane = tid & 31;
    const int w    = tid >> 5;
    const int bid = blockIdx.x;
    const int dir = bid & 1;
    const int ct  = (bid >> 1) & 7;
    const int rt  = bid >> 4;
    const int colBase = ct * 32;
    const int rowBase = rt * 32;
    const int r0 = w * 4;

    const float* W    = dir ? Wb : Wf;
    const float* bias = dir ? bb : bf;
    u64* out2 = (u64*)g_proj[dir];

    // W pairs for all 50 k2 (coalesced along cols)
    for (int idx = tid; idx < 3200; idx += 256) {
        int k2 = idx >> 6, c6 = idx & 63;
        int col = colBase + (c6 & 31) + ((c6 >> 5) << 8);
        W2[idx] = pk2(W[(2 * k2) * GG + col], W[(2 * k2 + 1) * GG + col]);
    }
    // emb pairs for 32 rows x 50 k2 (row-major gather)
    for (int idx = tid; idx < 1600; idx += 256) {
        int r = idx / 50, k2 = idx - r * 50;
        int row = rowBase + r;
        e2[k2 * EP2 + r] = (row < VOC)
            ? *(const u64*)&emb[row * EMBD + 2 * k2] : 0ULL;
    }
    __syncthreads();

    u64 acc[4][2];
    #pragma unroll
    for (int r = 0; r < 4; r++) { acc[r][0] = 0ULL; acc[r][1] = 0ULL; }

    #pragma unroll 5
    for (int k2 = 0; k2 < 50; k2++) {
        u64 wlo = W2[k2 * 64 + lane];
        u64 whi = W2[k2 * 64 + 32 + lane];
        ulonglong2 E0 = *(const ulonglong2*)&e2[k2 * EP2 + r0];
        ulonglong2 E1 = *(const ulonglong2*)&e2[k2 * EP2 + r0 + 2];
        acc[0][0] = fma2(E0.x, wlo, acc[0][0]); acc[0][1] = fma2(E0.x, whi, acc[0][1]);
        acc[1][0] = fma2(E0.y, wlo, acc[1][0]); acc[1][1] = fma2(E0.y, whi, acc[1][1]);
        acc[2][0] = fma2(E1.x, wlo, acc[2][0]); acc[2][1] = fma2(E1.x, whi, acc[2][1]);
        acc[3][0] = fma2(E1.y, wlo, acc[3][0]); acc[3][1] = fma2(E1.y, whi, acc[3][1]);
    }

    const float blo = bias[colBase + lane];
    const float bhi = bias[colBase + lane + 256];
    #pragma unroll
    for (int r = 0; r < 4; r++) {
        int row = rowBase + r0 + r;
        if (row < VOC) {
            float zlo = hadd2(acc[r][0]) + blo;
            float zhi = hadd2(acc[r][1]) + bhi;
            out2[(size_t)row * 256 + colBase + lane] = pk2(zlo, zhi);
        }
    }
}

// ---------------------------------------------------------------------------
// Persistent LSTM v3 (unchanged — 740us proven). grid 128 = 2 dirs x 64
// chunks of 8 batch rows. block 256; thread (m = tid&127, rg = tid>>7) owns
// gate cols {m, m+128, m+256, m+384} x rows 4rg..4rg+3.
// ---------------------------------------------------------------------------
#define KS2 50
__global__ __launch_bounds__(256, 1)
void lstm_kernel(const int* __restrict__ tokens)
{
    extern __shared__ char sm_raw[];
    u64* Up2    = (u64*)sm_raw;                    // [col][k2] stride 50
    u64* hbuf   = (u64*)(sm_raw + 204800);         // [buf][row*64+k2]
    int* tcache = (int*)(sm_raw + 212992);

    const int tid = threadIdx.x;
    const int dir = blockIdx.x >> 6;
    const int b0  = (blockIdx.x & 63) * 8;
    const int m   = tid & 127;
    const int rg  = tid >> 7;
    const u64* Ut = g_Ut[dir];
    const u64* proju = (const u64*)g_proj[dir];
    float* hout = g_h[dir];

    for (int idx = tid; idx < GG * KS2; idx += 256) {
        int col = idx / KS2, k2 = idx - col * KS2;
        Up2[idx] = Ut[col * 64 + k2];
    }
    u64 ur[4][14];
    #pragma unroll
    for (int c = 0; c < 4; c++) {
        const u64* src = &Ut[(m + 128 * c) * 64 + KS2];
        #pragma unroll
        for (int i = 0; i < 14; i++) ur[c][i] = src[i];
    }
    for (int idx = tid; idx < 8 * TT; idx += 256) {
        int r = idx / TT, t = idx % TT;
        tcache[idx] = tokens[(b0 + r) * TT + t];
    }
    hbuf[tid] = 0ULL;
    hbuf[tid + 256] = 0ULL;
    hbuf[tid + 512] = 0ULL;
    hbuf[tid + 768] = 0ULL;
    __syncthreads();

    u64 xA[4], xB[4];
    {
        int t0 = dir ? (TT - 1) : 0;
        #pragma unroll
        for (int rr = 0; rr < 4; rr++) {
            int tok = tcache[(4 * rg + rr) * TT + t0];
            xA[rr] = proju[(size_t)tok * 256 + m];
            xB[rr] = proju[(size_t)tok * 256 + m + 128];
        }
    }

    float cst[4] = {0.f, 0.f, 0.f, 0.f};

    for (int s = 0; s < TT; s++) {
        const int t = dir ? (TT - 1 - s) : s;
        const u64* hread = hbuf + (s & 1) * 512;
        u64* hwrite      = hbuf + ((s + 1) & 1) * 512;

        u64 a[4][4];
        #pragma unroll
        for (int rr = 0; rr < 4; rr++) {
            float xi, xg, xf, xo;
            upk2(xA[rr], xi, xg);
            upk2(xB[rr], xf, xo);
            a[rr][0] = pk2(xi, 0.0f);
            a[rr][1] = pk2(xf, 0.0f);
            a[rr][2] = pk2(xg, 0.0f);
            a[rr][3] = pk2(xo, 0.0f);
        }
        {
            int sn = (s + 1 < TT) ? (s + 1) : s;
            int tn = dir ? (TT - 1 - sn) : sn;
            #pragma unroll
            for (int rr = 0; rr < 4; rr++) {
                int tok = tcache[(4 * rg + rr) * TT + tn];
                xA[rr] = proju[(size_t)tok * 256 + m];
                xB[rr] = proju[(size_t)tok * 256 + m + 128];
            }
        }

        #pragma unroll 5
        for (int g = 0; g < 25; g++) {
            const int k2 = 2 * g;
            ulonglong2 H0 = *(const ulonglong2*)&hread[(4 * rg + 0) * 64 + k2];
            ulonglong2 H1 = *(const ulonglong2*)&hread[(4 * rg + 1) * 64 + k2];
            ulonglong2 H2 = *(const ulonglong2*)&hread[(4 * rg + 2) * 64 + k2];
            ulonglong2 H3 = *(const ulonglong2*)&hread[(4 * rg + 3) * 64 + k2];
            #pragma unroll
            for (int c = 0; c < 4; c++) {
                ulonglong2 U = *(const ulonglong2*)&Up2[(m + 128 * c) * KS2 + k2];
                a[0][c] = fma2(H0.x, U.x, a[0][c]); a[0][c] = fma2(H0.y, U.y, a[0][c]);
                a[1][c] = fma2(H1.x, U.x, a[1][c]); a[1][c] = fma2(H1.y, U.y, a[1][c]);
                a[2][c] = fma2(H2.x, U.x, a[2][c]); a[2][c] = fma2(H2.y, U.y, a[2][c]);
                a[3][c] = fma2(H3.x, U.x, a[3][c]); a[3][c] = fma2(H3.y, U.y, a[3][c]);
            }
        }
        #pragma unroll
        for (int g = 0; g < 7; g++) {
            const int k2 = KS2 + 2 * g;
            ulonglong2 H0 = *(const ulonglong2*)&hread[(4 * rg + 0) * 64 + k2];
            ulonglong2 H1 = *(const ulonglong2*)&hread[(4 * rg + 1) * 64 + k2];
            ulonglong2 H2 = *(const ulonglong2*)&hread[(4 * rg + 2) * 64 + k2];
            ulonglong2 H3 = *(const ulonglong2*)&hread[(4 * rg + 3) * 64 + k2];
            #pragma unroll
            for (int c = 0; c < 4; c++) {
                u64 u0 = ur[c][2 * g], u1 = ur[c][2 * g + 1];
                a[0][c] = fma2(H0.x, u0, a[0][c]); a[0][c] = fma2(H0.y, u1, a[0][c]);
                a[1][c] = fma2(H1.x, u0, a[1][c]); a[1][c] = fma2(H1.y, u1, a[1][c]);
                a[2][c] = fma2(H2.x, u0, a[2][c]); a[2][c] = fma2(H2.y, u1, a[2][c]);
                a[3][c] = fma2(H3.x, u0, a[3][c]); a[3][c] = fma2(H3.y, u1, a[3][c]);
            }
        }

        #pragma unroll
        for (int rr = 0; rr < 4; rr++) {
            float zi = hadd2(a[rr][0]);
            float zf = hadd2(a[rr][1]);
            float zg = hadd2(a[rr][2]);
            float zo = hadd2(a[rr][3]);
            float ii = sigf(zi);
            float ff = sigf(zf);
            float gg = fmaxf(zg, 0.0f);
            float oo = sigf(zo);
            float c  = ff * cst[rr] + ii * gg;
            cst[rr] = c;
            float h = oo * fmaxf(c, 0.0f);
            ((float*)&hwrite[(4 * rg + rr) * 64])[m] = h;
            hout[((size_t)(b0 + 4 * rg + rr) * TT + t) * HID + m] = h;
        }
        __syncthreads();
    }
}

// ---------------------------------------------------------------------------
// Head v2 (unchanged): BN pre-folded, transposed float4 weights.
// ---------------------------------------------------------------------------
__global__ __launch_bounds__(256, 4)
void head_kernel(float* __restrict__ out)
{
    __shared__ float4 Wt4[NCLS][64];
    __shared__ float bsm[NCLS];

    const int tid = threadIdx.x;
    for (int idx = tid; idx < NCLS * 64; idx += 256)
        ((float4*)Wt4)[idx] = ((const float4*)g_Wp)[idx];
    if (tid < NCLS) bsm[tid] = g_bp[tid];
    __syncthreads();

    const int wid  = tid >> 5;
    const int lane = tid & 31;
    const int pos  = blockIdx.x * 8 + wid;

    float4 hf = *(const float4*)&g_h[0][(size_t)pos * HID + lane * 4];
    float4 hb = *(const float4*)&g_h[1][(size_t)pos * HID + lane * 4];

    float acc[NCLS];
    #pragma unroll
    for (int c = 0; c < NCLS; c++) {
        float4 w0 = Wt4[c][lane];
        float4 w1 = Wt4[c][32 + lane];
        float s = hf.x * w0.x + hf.y * w0.y + hf.z * w0.z + hf.w * w0.w;
        s += hb.x * w1.x + hb.y * w1.y + hb.z * w1.z + hb.w * w1.w;
        acc[c] = s;
    }
    #pragma unroll
    for (int off = 16; off >= 1; off >>= 1) {
        #pragma unroll
        for (int c = 0; c < NCLS; c++)
            acc[c] += __shfl_xor_sync(0xFFFFFFFFu, acc[c], off);
    }

    if (lane == 0) {
        float z[NCLS], mx = -1e30f;
        #pragma unroll
        for (int c = 0; c < NCLS; c++) { z[c] = acc[c] + bsm[c]; mx = fmaxf(mx, z[c]); }
        float sum = 0.0f;
        #pragma unroll
        for (int c = 0; c < NCLS; c++) { z[c] = __expf(z[c] - mx); sum += z[c]; }
        float inv = __fdividef(1.0f, sum);
        #pragma unroll
        for (int c = 0; c < NCLS; c++) out[(size_t)pos * NCLS + c] = z[c] * inv;
    }
}

extern "C" void kernel_launch(void* const* d_in, const int* in_sizes, int n_in,
                              void* d_out, int out_size)
{
    const int*   tokens = (const int*)d_in[0];
    const float* emb    = (const float*)d_in[1];
    const float* Wf     = (const float*)d_in[2];
    const float* Uf     = (const float*)d_in[3];
    const float* bf     = (const float*)d_in[4];
    const float* Wb     = (const float*)d_in[5];
    const float* Ub     = (const float*)d_in[6];
    const float* bb     = (const float*)d_in[7];
    const float* gamma  = (const float*)d_in[8];
    const float* beta   = (const float*)d_in[9];
    const float* mmean  = (const float*)d_in[10];
    const float* mvar   = (const float*)d_in[11];
    const float* Wd     = (const float*)d_in[12];
    const float* bd     = (const float*)d_in[13];
    float* out = (float*)d_out;

    static bool attr_done = false;
    if (!attr_done) {
        cudaFuncSetAttribute(lstm_kernel, cudaFuncAttributeMaxDynamicSharedMemorySize, 219392);
        attr_done = true;
    }

    utrans_kernel<<<128, 512>>>(Uf, Ub);
    headprep_kernel<<<1, 256>>>(gamma, beta, mmean, mvar, Wd, bd);
    proj_kernel<<<938 * 8 * 2, 256>>>(emb, Wf, bf, Wb, bb);
    lstm_kernel<<<128, 256, 219392>>>(tokens);
    head_kernel<<<BSZ * TT / 8, 256>>>(out);
}

// round 16
// speedup vs baseline: 1.0444x; 1.0444x over previous
#include <cuda_runtime.h>
#include <cuda_bf16.h>

#define BSZ   512
#define TT    200
#define HID   128
#define GG    512
#define EMBD  100
#define VOC   30000
#define NCLS  9

// g_proj layout: per dir, u64[VOC][256]; slot j of row v = {col j, col j+256}
__device__ float g_proj[2][VOC * GG];
__device__ float g_h[2][BSZ * TT * HID];
// U transposed k-paired: [dir][col][k2], entry = {U[2k2][col], U[2k2+1][col]}
__device__ unsigned long long g_Ut[2][GG * 64];
// W k-paired: [dir][k2][col], entry = {W[2k2][col], W[2k2+1][col]}
__device__ unsigned long long g_Wp2[2][50 * GG];
// BN-folded dense: g_Wp[c][d] (c<9, d<256), g_bp[c]
__device__ float g_Wp[NCLS * 256];
__device__ float g_bp[16];

typedef unsigned long long u64;

__device__ __forceinline__ u64 pk2(float lo, float hi) {
    u64 r; asm("mov.b64 %0, {%1,%2};" : "=l"(r) : "f"(lo), "f"(hi)); return r;
}
__device__ __forceinline__ void upk2(u64 v, float& lo, float& hi) {
    asm("mov.b64 {%0,%1}, %2;" : "=f"(lo), "=f"(hi) : "l"(v));
}
__device__ __forceinline__ u64 fma2(u64 a, u64 b, u64 c) {
    u64 d; asm("fma.rn.f32x2 %0, %1, %2, %3;" : "=l"(d) : "l"(a), "l"(b), "l"(c)); return d;
}
__device__ __forceinline__ float hadd2(u64 v) {
    float lo, hi; upk2(v, lo, hi); return lo + hi;
}
__device__ __forceinline__ float sigf(float x) {
    return __fdividef(1.0f, 1.0f + __expf(-x));
}

// ---------------------------------------------------------------------------
// U transpose: g_Ut[dir][col*64+k2] = {U[2k2][col], U[2k2+1][col]}
// ---------------------------------------------------------------------------
__global__ void utrans_kernel(const float* __restrict__ Uf, const float* __restrict__ Ub)
{
    const int k2  = blockIdx.x & 63;
    const int dir = blockIdx.x >> 6;
    const float* U = dir ? Ub : Uf;
    const int col = threadIdx.x;
    g_Ut[dir][col * 64 + k2] = pk2(U[2 * k2 * GG + col], U[(2 * k2 + 1) * GG + col]);
}

// ---------------------------------------------------------------------------
// W pair prep: g_Wp2[dir][k2*512+col] = {W[2k2][col], W[2k2+1][col]}
// grid 100 = 2 dirs x 50 k2, block 512.
// ---------------------------------------------------------------------------
__global__ void wpair_kernel(const float* __restrict__ Wf, const float* __restrict__ Wb)
{
    const int k2  = blockIdx.x % 50;
    const int dir = blockIdx.x / 50;
    const float* W = dir ? Wb : Wf;
    const int col = threadIdx.x;
    g_Wp2[dir][k2 * GG + col] = pk2(W[2 * k2 * GG + col], W[(2 * k2 + 1) * GG + col]);
}

// ---------------------------------------------------------------------------
// Head prep: fold BN into dense.
// ---------------------------------------------------------------------------
__global__ void headprep_kernel(const float* __restrict__ gamma, const float* __restrict__ beta,
                                const float* __restrict__ mean,  const float* __restrict__ var,
                                const float* __restrict__ Wd,    const float* __restrict__ bd)
{
    __shared__ float sc[256], sh[256];
    const int tid = threadIdx.x;
    float rs = rsqrtf(var[tid] + 1e-3f);
    float s  = rs * gamma[tid];
    sc[tid] = s;
    sh[tid] = beta[tid] - mean[tid] * s;
    __syncthreads();
    for (int idx = tid; idx < NCLS * 256; idx += 256) {
        int c = idx >> 8, d = idx & 255;
        g_Wp[idx] = sc[d] * Wd[d * NCLS + c];
    }
    if (tid < NCLS) {
        float acc = bd[tid];
        for (int d = 0; d < 256; d++) acc += sh[d] * Wd[d * NCLS + tid];
        g_bp[tid] = acc;
    }
}

// ---------------------------------------------------------------------------
// proj v6: persistent workers, W resident, double-buffered 64-row e-tiles.
// grid 288 = 16 colcfg (dir, ct) x 18 workers; 2 CTAs/SM. block 256 = 8 warps,
// lane = slot (colBase+lane), warp = 8 rows. Worker iterates rowtiles
// rt = wk, wk+18, ... < 469 (64 rows each), prefetching next e-tile during
// compute. One barrier per tile.
// smem: W2[50*64] u64 (25600) + e2[2][50*66] u64 (52800) = 78400B.
// ---------------------------------------------------------------------------
#define EB 66
#define EBUF (50 * EB)
#define NROWT 469
__global__ __launch_bounds__(256, 2)
void proj_kernel(const float* __restrict__ emb,
                 const float* __restrict__ bf, const float* __restrict__ bb)
{
    extern __shared__ u64 psm[];
    u64* W2 = psm;            // [k2][c6]
    u64* e2 = psm + 3200;     // [2][k2][row]

    const int tid  = threadIdx.x;
    const int lane = tid & 31;
    const int w    = tid >> 5;
    const int cfg = blockIdx.x & 15;
    const int wk  = blockIdx.x >> 4;     // 0..17
    const int dir = cfg & 1;
    const int ct  = cfg >> 1;
    const int colBase = ct * 32;
    const int r0 = w * 8;

    const u64* Wp = g_Wp2[dir];
    const float* bias = dir ? bb : bf;
    u64* out2 = (u64*)g_proj[dir];

    // W tile: loaded ONCE per worker
    for (int idx = tid; idx < 3200; idx += 256) {
        int k2 = idx >> 6, c6 = idx & 63;
        int col = colBase + (c6 & 31) + ((c6 >> 5) << 8);
        W2[idx] = Wp[k2 * GG + col];
    }
    const float blo = bias[colBase + lane];
    const float bhi = bias[colBase + lane + 256];

    // first e-tile
    int rt = wk;
    {
        int rowBase = rt * 64;
        for (int idx = tid; idx < 3200; idx += 256) {
            int k2 = idx >> 6, r = idx & 63;
            int row = rowBase + r;
            e2[k2 * EB + r] = (row < VOC)
                ? *(const u64*)&emb[row * EMBD + 2 * k2] : 0ULL;
        }
    }
    __syncthreads();

    for (int i = 0; rt < NROWT; i++, rt += 18) {
        const int buf = i & 1;
        const int rowBase = rt * 64;

        // prefetch next tile into the other buffer (hidden under compute)
        const int rtn = rt + 18;
        if (rtn < NROWT) {
            int rbn = rtn * 64;
            u64* dst = e2 + (buf ^ 1) * EBUF;
            for (int idx = tid; idx < 3200; idx += 256) {
                int k2 = idx >> 6, r = idx & 63;
                int row = rbn + r;
                dst[k2 * EB + r] = (row < VOC)
                    ? *(const u64*)&emb[row * EMBD + 2 * k2] : 0ULL;
            }
        }

        // compute current tile
        const u64* eb = e2 + buf * EBUF;
        u64 acc[8][2];
        #pragma unroll
        for (int r = 0; r < 8; r++) { acc[r][0] = 0ULL; acc[r][1] = 0ULL; }

        #pragma unroll 5
        for (int k2 = 0; k2 < 50; k2++) {
            u64 wlo = W2[k2 * 64 + lane];
            u64 whi = W2[k2 * 64 + 32 + lane];
            ulonglong2 E0 = *(const ulonglong2*)&eb[k2 * EB + r0];
            ulonglong2 E1 = *(const ulonglong2*)&eb[k2 * EB + r0 + 2];
            ulonglong2 E2 = *(const ulonglong2*)&eb[k2 * EB + r0 + 4];
            ulonglong2 E3 = *(const ulonglong2*)&eb[k2 * EB + r0 + 6];
            acc[0][0] = fma2(E0.x, wlo, acc[0][0]); acc[0][1] = fma2(E0.x, whi, acc[0][1]);
            acc[1][0] = fma2(E0.y, wlo, acc[1][0]); acc[1][1] = fma2(E0.y, whi, acc[1][1]);
            acc[2][0] = fma2(E1.x, wlo, acc[2][0]); acc[2][1] = fma2(E1.x, whi, acc[2][1]);
            acc[3][0] = fma2(E1.y, wlo, acc[3][0]); acc[3][1] = fma2(E1.y, whi, acc[3][1]);
            acc[4][0] = fma2(E2.x, wlo, acc[4][0]); acc[4][1] = fma2(E2.x, whi, acc[4][1]);
            acc[5][0] = fma2(E2.y, wlo, acc[5][0]); acc[5][1] = fma2(E2.y, whi, acc[5][1]);
            acc[6][0] = fma2(E3.x, wlo, acc[6][0]); acc[6][1] = fma2(E3.x, whi, acc[6][1]);
            acc[7][0] = fma2(E3.y, wlo, acc[7][0]); acc[7][1] = fma2(E3.y, whi, acc[7][1]);
        }

        #pragma unroll
        for (int r = 0; r < 8; r++) {
            int row = rowBase + r0 + r;
            if (row < VOC) {
                float zlo = hadd2(acc[r][0]) + blo;
                float zhi = hadd2(acc[r][1]) + bhi;
                out2[(size_t)row * 256 + colBase + lane] = pk2(zlo, zhi);
            }
        }
        __syncthreads();
    }
}

// ---------------------------------------------------------------------------
// Persistent LSTM v3 (unchanged — 740us proven). grid 128 = 2 dirs x 64
// chunks of 8 batch rows. block 256; thread (m = tid&127, rg = tid>>7) owns
// gate cols {m, m+128, m+256, m+384} x rows 4rg..4rg+3.
// ---------------------------------------------------------------------------
#define KS2 50
__global__ __launch_bounds__(256, 1)
void lstm_kernel(const int* __restrict__ tokens)
{
    extern __shared__ char sm_raw[];
    u64* Up2    = (u64*)sm_raw;                    // [col][k2] stride 50
    u64* hbuf   = (u64*)(sm_raw + 204800);         // [buf][row*64+k2]
    int* tcache = (int*)(sm_raw + 212992);

    const int tid = threadIdx.x;
    const int dir = blockIdx.x >> 6;
    const int b0  = (blockIdx.x & 63) * 8;
    const int m   = tid & 127;
    const int rg  = tid >> 7;
    const u64* Ut = g_Ut[dir];
    const u64* proju = (const u64*)g_proj[dir];
    float* hout = g_h[dir];

    for (int idx = tid; idx < GG * KS2; idx += 256) {
        int col = idx / KS2, k2 = idx - col * KS2;
        Up2[idx] = Ut[col * 64 + k2];
    }
    u64 ur[4][14];
    #pragma unroll
    for (int c = 0; c < 4; c++) {
        const u64* src = &Ut[(m + 128 * c) * 64 + KS2];
        #pragma unroll
        for (int i = 0; i < 14; i++) ur[c][i] = src[i];
    }
    for (int idx = tid; idx < 8 * TT; idx += 256) {
        int r = idx / TT, t = idx % TT;
        tcache[idx] = tokens[(b0 + r) * TT + t];
    }
    hbuf[tid] = 0ULL;
    hbuf[tid + 256] = 0ULL;
    hbuf[tid + 512] = 0ULL;
    hbuf[tid + 768] = 0ULL;
    __syncthreads();

    u64 xA[4], xB[4];
    {
        int t0 = dir ? (TT - 1) : 0;
        #pragma unroll
        for (int rr = 0; rr < 4; rr++) {
            int tok = tcache[(4 * rg + rr) * TT + t0];
            xA[rr] = proju[(size_t)tok * 256 + m];
            xB[rr] = proju[(size_t)tok * 256 + m + 128];
        }
    }

    float cst[4] = {0.f, 0.f, 0.f, 0.f};

    for (int s = 0; s < TT; s++) {
        const int t = dir ? (TT - 1 - s) : s;
        const u64* hread = hbuf + (s & 1) * 512;
        u64* hwrite      = hbuf + ((s + 1) & 1) * 512;

        u64 a[4][4];
        #pragma unroll
        for (int rr = 0; rr < 4; rr++) {
            float xi, xg, xf, xo;
            upk2(xA[rr], xi, xg);
            upk2(xB[rr], xf, xo);
            a[rr][0] = pk2(xi, 0.0f);
            a[rr][1] = pk2(xf, 0.0f);
            a[rr][2] = pk2(xg, 0.0f);
            a[rr][3] = pk2(xo, 0.0f);
        }
        {
            int sn = (s + 1 < TT) ? (s + 1) : s;
            int tn = dir ? (TT - 1 - sn) : sn;
            #pragma unroll
            for (int rr = 0; rr < 4; rr++) {
                int tok = tcache[(4 * rg + rr) * TT + tn];
                xA[rr] = proju[(size_t)tok * 256 + m];
                xB[rr] = proju[(size_t)tok * 256 + m + 128];
            }
        }

        #pragma unroll 5
        for (int g = 0; g < 25; g++) {
            const int k2 = 2 * g;
            ulonglong2 H0 = *(const ulonglong2*)&hread[(4 * rg + 0) * 64 + k2];
            ulonglong2 H1 = *(const ulonglong2*)&hread[(4 * rg + 1) * 64 + k2];
            ulonglong2 H2 = *(const ulonglong2*)&hread[(4 * rg + 2) * 64 + k2];
            ulonglong2 H3 = *(const ulonglong2*)&hread[(4 * rg + 3) * 64 + k2];
            #pragma unroll
            for (int c = 0; c < 4; c++) {
                ulonglong2 U = *(const ulonglong2*)&Up2[(m + 128 * c) * KS2 + k2];
                a[0][c] = fma2(H0.x, U.x, a[0][c]); a[0][c] = fma2(H0.y, U.y, a[0][c]);
                a[1][c] = fma2(H1.x, U.x, a[1][c]); a[1][c] = fma2(H1.y, U.y, a[1][c]);
                a[2][c] = fma2(H2.x, U.x, a[2][c]); a[2][c] = fma2(H2.y, U.y, a[2][c]);
                a[3][c] = fma2(H3.x, U.x, a[3][c]); a[3][c] = fma2(H3.y, U.y, a[3][c]);
            }
        }
        #pragma unroll
        for (int g = 0; g < 7; g++) {
            const int k2 = KS2 + 2 * g;
            ulonglong2 H0 = *(const ulonglong2*)&hread[(4 * rg + 0) * 64 + k2];
            ulonglong2 H1 = *(const ulonglong2*)&hread[(4 * rg + 1) * 64 + k2];
            ulonglong2 H2 = *(const ulonglong2*)&hread[(4 * rg + 2) * 64 + k2];
            ulonglong2 H3 = *(const ulonglong2*)&hread[(4 * rg + 3) * 64 + k2];
            #pragma unroll
            for (int c = 0; c < 4; c++) {
                u64 u0 = ur[c][2 * g], u1 = ur[c][2 * g + 1];
                a[0][c] = fma2(H0.x, u0, a[0][c]); a[0][c] = fma2(H0.y, u1, a[0][c]);
                a[1][c] = fma2(H1.x, u0, a[1][c]); a[1][c] = fma2(H1.y, u1, a[1][c]);
                a[2][c] = fma2(H2.x, u0, a[2][c]); a[2][c] = fma2(H2.y, u1, a[2][c]);
                a[3][c] = fma2(H3.x, u0, a[3][c]); a[3][c] = fma2(H3.y, u1, a[3][c]);
            }
        }

        #pragma unroll
        for (int rr = 0; rr < 4; rr++) {
            float zi = hadd2(a[rr][0]);
            float zf = hadd2(a[rr][1]);
            float zg = hadd2(a[rr][2]);
            float zo = hadd2(a[rr][3]);
            float ii = sigf(zi);
            float ff = sigf(zf);
            float gg = fmaxf(zg, 0.0f);
            float oo = sigf(zo);
            float c  = ff * cst[rr] + ii * gg;
            cst[rr] = c;
            float h = oo * fmaxf(c, 0.0f);
            ((float*)&hwrite[(4 * rg + rr) * 64])[m] = h;
            hout[((size_t)(b0 + 4 * rg + rr) * TT + t) * HID + m] = h;
        }
        __syncthreads();
    }
}

// ---------------------------------------------------------------------------
// Head v2 (unchanged): BN pre-folded, transposed float4 weights.
// ---------------------------------------------------------------------------
__global__ __launch_bounds__(256, 4)
void head_kernel(float* __restrict__ out)
{
    __shared__ float4 Wt4[NCLS][64];
    __shared__ float bsm[NCLS];

    const int tid = threadIdx.x;
    for (int idx = tid; idx < NCLS * 64; idx += 256)
        ((float4*)Wt4)[idx] = ((const float4*)g_Wp)[idx];
    if (tid < NCLS) bsm[tid] = g_bp[tid];
    __syncthreads();

    const int wid  = tid >> 5;
    const int lane = tid & 31;
    const int pos  = blockIdx.x * 8 + wid;

    float4 hf = *(const float4*)&g_h[0][(size_t)pos * HID + lane * 4];
    float4 hb = *(const float4*)&g_h[1][(size_t)pos * HID + lane * 4];

    float acc[NCLS];
    #pragma unroll
    for (int c = 0; c < NCLS; c++) {
        float4 w0 = Wt4[c][lane];
        float4 w1 = Wt4[c][32 + lane];
        float s = hf.x * w0.x + hf.y * w0.y + hf.z * w0.z + hf.w * w0.w;
        s += hb.x * w1.x + hb.y * w1.y + hb.z * w1.z + hb.w * w1.w;
        acc[c] = s;
    }
    #pragma unroll
    for (int off = 16; off >= 1; off >>= 1) {
        #pragma unroll
        for (int c = 0; c < NCLS; c++)
            acc[c] += __shfl_xor_sync(0xFFFFFFFFu, acc[c], off);
    }

    if (lane == 0) {
        float z[NCLS], mx = -1e30f;
        #pragma unroll
        for (int c = 0; c < NCLS; c++) { z[c] = acc[c] + bsm[c]; mx = fmaxf(mx, z[c]); }
        float sum = 0.0f;
        #pragma unroll
        for (int c = 0; c < NCLS; c++) { z[c] = __expf(z[c] - mx); sum += z[c]; }
        float inv = __fdividef(1.0f, sum);
        #pragma unroll
        for (int c = 0; c < NCLS; c++) out[(size_t)pos * NCLS + c] = z[c] * inv;
    }
}

extern "C" void kernel_launch(void* const* d_in, const int* in_sizes, int n_in,
                              void* d_out, int out_size)
{
    const int*   tokens = (const int*)d_in[0];
    const float* emb    = (const float*)d_in[1];
    const float* Wf     = (const float*)d_in[2];
    const float* Uf     = (const float*)d_in[3];
    const float* bf     = (const float*)d_in[4];
    const float* Wb     = (const float*)d_in[5];
    const float* Ub     = (const float*)d_in[6];
    const float* bb     = (const float*)d_in[7];
    const float* gamma  = (const float*)d_in[8];
    const float* beta   = (const float*)d_in[9];
    const float* mmean  = (const float*)d_in[10];
    const float* mvar   = (const float*)d_in[11];
    const float* Wd     = (const float*)d_in[12];
    const float* bd     = (const float*)d_in[13];
    float* out = (float*)d_out;

    static bool attr_done = false;
    if (!attr_done) {
        cudaFuncSetAttribute(lstm_kernel, cudaFuncAttributeMaxDynamicSharedMemorySize, 219392);
        cudaFuncSetAttribute(proj_kernel, cudaFuncAttributeMaxDynamicSharedMemorySize, 78400);
        attr_done = true;
    }

    utrans_kernel<<<128, 512>>>(Uf, Ub);
    wpair_kernel<<<100, 512>>>(Wf, Wb);
    headprep_kernel<<<1, 256>>>(gamma, beta, mmean, mvar, Wd, bd);
    proj_kernel<<<288, 256, 78400>>>(emb, bf, bb);
    lstm_kernel<<<128, 256, 219392>>>(tokens);
    head_kernel<<<BSZ * TT / 8, 256>>>(out);
}

// round 17
// speedup vs baseline: 1.0883x; 1.0421x over previous
#include <cuda_runtime.h>
#include <cuda_bf16.h>

#define BSZ   512
#define TT    200
#define HID   128
#define GG    512
#define EMBD  100
#define VOC   30000
#define NCLS  9

// g_proj layout: per dir, u64[VOC][256]; slot j of row v = {col j, col j+256}
__device__ float g_proj[2][VOC * GG];
__device__ float g_h[2][BSZ * TT * HID];
// U transposed k-paired: [dir][col][k2], entry = {U[2k2][col], U[2k2+1][col]}
__device__ unsigned long long g_Ut[2][GG * 64];
// BN-folded dense: g_Wp[c][d] (c<9, d<256), g_bp[c]
__device__ float g_Wp[NCLS * 256];
__device__ float g_bp[16];

typedef unsigned long long u64;

__device__ __forceinline__ u64 pk2(float lo, float hi) {
    u64 r; asm("mov.b64 %0, {%1,%2};" : "=l"(r) : "f"(lo), "f"(hi)); return r;
}
__device__ __forceinline__ void upk2(u64 v, float& lo, float& hi) {
    asm("mov.b64 {%0,%1}, %2;" : "=f"(lo), "=f"(hi) : "l"(v));
}
__device__ __forceinline__ u64 fma2(u64 a, u64 b, u64 c) {
    u64 d; asm("fma.rn.f32x2 %0, %1, %2, %3;" : "=l"(d) : "l"(a), "l"(b), "l"(c)); return d;
}
__device__ __forceinline__ float hadd2(u64 v) {
    float lo, hi; upk2(v, lo, hi); return lo + hi;
}
__device__ __forceinline__ float sigf(float x) {
    return __fdividef(1.0f, 1.0f + __expf(-x));
}

// ---------------------------------------------------------------------------
// U transpose: g_Ut[dir][col*64+k2] = {U[2k2][col], U[2k2+1][col]}
// ---------------------------------------------------------------------------
__global__ void utrans_kernel(const float* __restrict__ Uf, const float* __restrict__ Ub)
{
    const int k2  = blockIdx.x & 63;
    const int dir = blockIdx.x >> 6;
    const float* U = dir ? Ub : Uf;
    const int col = threadIdx.x;
    g_Ut[dir][col * 64 + k2] = pk2(U[2 * k2 * GG + col], U[(2 * k2 + 1) * GG + col]);
}

// ---------------------------------------------------------------------------
// Head prep: fold BN into dense.
// ---------------------------------------------------------------------------
__global__ void headprep_kernel(const float* __restrict__ gamma, const float* __restrict__ beta,
                                const float* __restrict__ mean,  const float* __restrict__ var,
                                const float* __restrict__ Wd,    const float* __restrict__ bd)
{
    __shared__ float sc[256], sh[256];
    const int tid = threadIdx.x;
    float rs = rsqrtf(var[tid] + 1e-3f);
    float s  = rs * gamma[tid];
    sc[tid] = s;
    sh[tid] = beta[tid] - mean[tid] * s;
    __syncthreads();
    for (int idx = tid; idx < NCLS * 256; idx += 256) {
        int c = idx >> 8, d = idx & 255;
        g_Wp[idx] = sc[d] * Wd[d * NCLS + c];
    }
    if (tid < NCLS) {
        float acc = bd[tid];
        for (int d = 0; d < 256; d++) acc += sh[d] * Wd[d * NCLS + tid];
        g_bp[tid] = acc;
    }
}

// ---------------------------------------------------------------------------
// proj v4 (best measured): ALL k in smem up front, one sync, 50 k2 straight.
// CTA tile: 128 vocab rows x 32 slots. block 256 = 8 warps; lane = slot,
// warp = 16 rows. smem 77600B -> 2 CTAs/SM. grid = 235 x 8 x 2 = 3760.
// ---------------------------------------------------------------------------
#define EP 130
__global__ __launch_bounds__(256, 2)
void proj_kernel(const float* __restrict__ emb,
                 const float* __restrict__ Wf, const float* __restrict__ bf,
                 const float* __restrict__ Wb, const float* __restrict__ bb)
{
    __shared__ u64 W2[50 * 64];     // [k2][c6]: c6<32 -> col, c6>=32 -> col+256
    __shared__ u64 e2[50 * EP];     // [k2][row]

    const int tid  = threadIdx.x;
    const int lane = tid & 31;
    const int w    = tid >> 5;
    const int bid = blockIdx.x;
    const int dir = bid & 1;
    const int ct  = (bid >> 1) & 7;
    const int rt  = bid >> 4;
    const int colBase = ct * 32;
    const int rowBase = rt * 128;
    const int r0 = w * 16;

    const float* W    = dir ? Wb : Wf;
    const float* bias = dir ? bb : bf;
    u64* out2 = (u64*)g_proj[dir];

    for (int idx = tid; idx < 3200; idx += 256) {
        int k2 = idx >> 6, c6 = idx & 63;
        int col = colBase + (c6 & 31) + ((c6 >> 5) << 8);
        W2[idx] = pk2(W[(2 * k2) * GG + col], W[(2 * k2 + 1) * GG + col]);
    }
    for (int idx = tid; idx < 6400; idx += 256) {
        int r = idx / 50, k2 = idx - r * 50;
        int row = rowBase + r;
        e2[k2 * EP + r] = (row < VOC)
            ? *(const u64*)&emb[row * EMBD + 2 * k2] : 0ULL;
    }
    __syncthreads();

    u64 acc[16][2];
    #pragma unroll
    for (int r = 0; r < 16; r++) { acc[r][0] = 0ULL; acc[r][1] = 0ULL; }

    #pragma unroll 5
    for (int k2 = 0; k2 < 50; k2++) {
        u64 wlo = W2[k2 * 64 + lane];
        u64 whi = W2[k2 * 64 + 32 + lane];
        ulonglong2 E[8];
        #pragma unroll
        for (int j = 0; j < 8; j++)
            E[j] = *(const ulonglong2*)&e2[k2 * EP + r0 + 2 * j];
        #pragma unroll
        for (int j = 0; j < 8; j++) {
            acc[2*j][0]   = fma2(E[j].x, wlo, acc[2*j][0]);
            acc[2*j][1]   = fma2(E[j].x, whi, acc[2*j][1]);
            acc[2*j+1][0] = fma2(E[j].y, wlo, acc[2*j+1][0]);
            acc[2*j+1][1] = fma2(E[j].y, whi, acc[2*j+1][1]);
        }
    }

    const float blo = bias[colBase + lane];
    const float bhi = bias[colBase + lane + 256];
    #pragma unroll
    for (int r = 0; r < 16; r++) {
        int row = rowBase + r0 + r;
        if (row < VOC) {
            float zlo = hadd2(acc[r][0]) + blo;
            float zhi = hadd2(acc[r][1]) + bhi;
            out2[(size_t)row * 256 + colBase + lane] = pk2(zlo, zhi);
        }
    }
}

// ---------------------------------------------------------------------------
// Persistent LSTM v3 (best measured — 738us). grid 128 = 2 dirs x 64 chunks
// of 8 batch rows. block 256; thread (m = tid&127, rg = tid>>7) owns gate
// cols {m, m+128, m+256, m+384} x rows 4rg..4rg+3. U: k2 0..49 smem
// [col][50] (stride-50 conflict-free), k2 50..63 regs. 1 barrier/step.
// ---------------------------------------------------------------------------
#define KS2 50
__global__ __launch_bounds__(256, 1)
void lstm_kernel(const int* __restrict__ tokens)
{
    extern __shared__ char sm_raw[];
    u64* Up2    = (u64*)sm_raw;                    // [col][k2] stride 50
    u64* hbuf   = (u64*)(sm_raw + 204800);         // [buf][row*64+k2]
    int* tcache = (int*)(sm_raw + 212992);

    const int tid = threadIdx.x;
    const int dir = blockIdx.x >> 6;
    const int b0  = (blockIdx.x & 63) * 8;
    const int m   = tid & 127;
    const int rg  = tid >> 7;
    const u64* Ut = g_Ut[dir];
    const u64* proju = (const u64*)g_proj[dir];
    float* hout = g_h[dir];

    for (int idx = tid; idx < GG * KS2; idx += 256) {
        int col = idx / KS2, k2 = idx - col * KS2;
        Up2[idx] = Ut[col * 64 + k2];
    }
    u64 ur[4][14];
    #pragma unroll
    for (int c = 0; c < 4; c++) {
        const u64* src = &Ut[(m + 128 * c) * 64 + KS2];
        #pragma unroll
        for (int i = 0; i < 14; i++) ur[c][i] = src[i];
    }
    for (int idx = tid; idx < 8 * TT; idx += 256) {
        int r = idx / TT, t = idx % TT;
        tcache[idx] = tokens[(b0 + r) * TT + t];
    }
    hbuf[tid] = 0ULL;
    hbuf[tid + 256] = 0ULL;
    hbuf[tid + 512] = 0ULL;
    hbuf[tid + 768] = 0ULL;
    __syncthreads();

    u64 xA[4], xB[4];
    {
        int t0 = dir ? (TT - 1) : 0;
        #pragma unroll
        for (int rr = 0; rr < 4; rr++) {
            int tok = tcache[(4 * rg + rr) * TT + t0];
            xA[rr] = proju[(size_t)tok * 256 + m];
            xB[rr] = proju[(size_t)tok * 256 + m + 128];
        }
    }

    float cst[4] = {0.f, 0.f, 0.f, 0.f};

    for (int s = 0; s < TT; s++) {
        const int t = dir ? (TT - 1 - s) : s;
        const u64* hread = hbuf + (s & 1) * 512;
        u64* hwrite      = hbuf + ((s + 1) & 1) * 512;

        u64 a[4][4];
        #pragma unroll
        for (int rr = 0; rr < 4; rr++) {
            float xi, xg, xf, xo;
            upk2(xA[rr], xi, xg);
            upk2(xB[rr], xf, xo);
            a[rr][0] = pk2(xi, 0.0f);
            a[rr][1] = pk2(xf, 0.0f);
            a[rr][2] = pk2(xg, 0.0f);
            a[rr][3] = pk2(xo, 0.0f);
        }
        {
            int sn = (s + 1 < TT) ? (s + 1) : s;
            int tn = dir ? (TT - 1 - sn) : sn;
            #pragma unroll
            for (int rr = 0; rr < 4; rr++) {
                int tok = tcache[(4 * rg + rr) * TT + tn];
                xA[rr] = proju[(size_t)tok * 256 + m];
                xB[rr] = proju[(size_t)tok * 256 + m + 128];
            }
        }

        #pragma unroll 5
        for (int g = 0; g < 25; g++) {
            const int k2 = 2 * g;
            ulonglong2 H0 = *(const ulonglong2*)&hread[(4 * rg + 0) * 64 + k2];
            ulonglong2 H1 = *(const ulonglong2*)&hread[(4 * rg + 1) * 64 + k2];
            ulonglong2 H2 = *(const ulonglong2*)&hread[(4 * rg + 2) * 64 + k2];
            ulonglong2 H3 = *(const ulonglong2*)&hread[(4 * rg + 3) * 64 + k2];
            #pragma unroll
            for (int c = 0; c < 4; c++) {
                ulonglong2 U = *(const ulonglong2*)&Up2[(m + 128 * c) * KS2 + k2];
                a[0][c] = fma2(H0.x, U.x, a[0][c]); a[0][c] = fma2(H0.y, U.y, a[0][c]);
                a[1][c] = fma2(H1.x, U.x, a[1][c]); a[1][c] = fma2(H1.y, U.y, a[1][c]);
                a[2][c] = fma2(H2.x, U.x, a[2][c]); a[2][c] = fma2(H2.y, U.y, a[2][c]);
                a[3][c] = fma2(H3.x, U.x, a[3][c]); a[3][c] = fma2(H3.y, U.y, a[3][c]);
            }
        }
        #pragma unroll
        for (int g = 0; g < 7; g++) {
            const int k2 = KS2 + 2 * g;
            ulonglong2 H0 = *(const ulonglong2*)&hread[(4 * rg + 0) * 64 + k2];
            ulonglong2 H1 = *(const ulonglong2*)&hread[(4 * rg + 1) * 64 + k2];
            ulonglong2 H2 = *(const ulonglong2*)&hread[(4 * rg + 2) * 64 + k2];
            ulonglong2 H3 = *(const ulonglong2*)&hread[(4 * rg + 3) * 64 + k2];
            #pragma unroll
            for (int c = 0; c < 4; c++) {
                u64 u0 = ur[c][2 * g], u1 = ur[c][2 * g + 1];
                a[0][c] = fma2(H0.x, u0, a[0][c]); a[0][c] = fma2(H0.y, u1, a[0][c]);
                a[1][c] = fma2(H1.x, u0, a[1][c]); a[1][c] = fma2(H1.y, u1, a[1][c]);
                a[2][c] = fma2(H2.x, u0, a[2][c]); a[2][c] = fma2(H2.y, u1, a[2][c]);
                a[3][c] = fma2(H3.x, u0, a[3][c]); a[3][c] = fma2(H3.y, u1, a[3][c]);
            }
        }

        #pragma unroll
        for (int rr = 0; rr < 4; rr++) {
            float zi = hadd2(a[rr][0]);
            float zf = hadd2(a[rr][1]);
            float zg = hadd2(a[rr][2]);
            float zo = hadd2(a[rr][3]);
            float ii = sigf(zi);
            float ff = sigf(zf);
            float gg = fmaxf(zg, 0.0f);
            float oo = sigf(zo);
            float c  = ff * cst[rr] + ii * gg;
            cst[rr] = c;
            float h = oo * fmaxf(c, 0.0f);
            ((float*)&hwrite[(4 * rg + rr) * 64])[m] = h;
            hout[((size_t)(b0 + 4 * rg + rr) * TT + t) * HID + m] = h;
        }
        __syncthreads();
    }
}

// ---------------------------------------------------------------------------
// Head v2 (unchanged): BN pre-folded, transposed float4 weights.
// ---------------------------------------------------------------------------
__global__ __launch_bounds__(256, 4)
void head_kernel(float* __restrict__ out)
{
    __shared__ float4 Wt4[NCLS][64];
    __shared__ float bsm[NCLS];

    const int tid = threadIdx.x;
    for (int idx = tid; idx < NCLS * 64; idx += 256)
        ((float4*)Wt4)[idx] = ((const float4*)g_Wp)[idx];
    if (tid < NCLS) bsm[tid] = g_bp[tid];
    __syncthreads();

    const int wid  = tid >> 5;
    const int lane = tid & 31;
    const int pos  = blockIdx.x * 8 + wid;

    float4 hf = *(const float4*)&g_h[0][(size_t)pos * HID + lane * 4];
    float4 hb = *(const float4*)&g_h[1][(size_t)pos * HID + lane * 4];

    float acc[NCLS];
    #pragma unroll
    for (int c = 0; c < NCLS; c++) {
        float4 w0 = Wt4[c][lane];
        float4 w1 = Wt4[c][32 + lane];
        float s = hf.x * w0.x + hf.y * w0.y + hf.z * w0.z + hf.w * w0.w;
        s += hb.x * w1.x + hb.y * w1.y + hb.z * w1.z + hb.w * w1.w;
        acc[c] = s;
    }
    #pragma unroll
    for (int off = 16; off >= 1; off >>= 1) {
        #pragma unroll
        for (int c = 0; c < NCLS; c++)
            acc[c] += __shfl_xor_sync(0xFFFFFFFFu, acc[c], off);
    }

    if (lane == 0) {
        float z[NCLS], mx = -1e30f;
        #pragma unroll
        for (int c = 0; c < NCLS; c++) { z[c] = acc[c] + bsm[c]; mx = fmaxf(mx, z[c]); }
        float sum = 0.0f;
        #pragma unroll
        for (int c = 0; c < NCLS; c++) { z[c] = __expf(z[c] - mx); sum += z[c]; }
        float inv = __fdividef(1.0f, sum);
        #pragma unroll
        for (int c = 0; c < NCLS; c++) out[(size_t)pos * NCLS + c] = z[c] * inv;
    }
}

extern "C" void kernel_launch(void* const* d_in, const int* in_sizes, int n_in,
                              void* d_out, int out_size)
{
    const int*   tokens = (const int*)d_in[0];
    const float* emb    = (const float*)d_in[1];
    const float* Wf     = (const float*)d_in[2];
    const float* Uf     = (const float*)d_in[3];
    const float* bf     = (const float*)d_in[4];
    const float* Wb     = (const float*)d_in[5];
    const float* Ub     = (const float*)d_in[6];
    const float* bb     = (const float*)d_in[7];
    const float* gamma  = (const float*)d_in[8];
    const float* beta   = (const float*)d_in[9];
    const float* mmean  = (const float*)d_in[10];
    const float* mvar   = (const float*)d_in[11];
    const float* Wd     = (const float*)d_in[12];
    const float* bd     = (const float*)d_in[13];
    float* out = (float*)d_out;

    static bool attr_done = false;
    if (!attr_done) {
        cudaFuncSetAttribute(lstm_kernel, cudaFuncAttributeMaxDynamicSharedMemorySize, 219392);
        attr_done = true;
    }

    utrans_kernel<<<128, 512>>>(Uf, Ub);
    headprep_kernel<<<1, 256>>>(gamma, beta, mmean, mvar, Wd, bd);
    proj_kernel<<<235 * 8 * 2, 256>>>(emb, Wf, bf, Wb, bb);
    lstm_kernel<<<128, 256, 219392>>>(tokens);
    head_kernel<<<BSZ * TT / 8, 256>>>(out);
}